// round 7
// baseline (speedup 1.0000x reference)
#include <cuda_runtime.h>

namespace {
constexpr int B = 4, S = 2048, D = 64, KS = 8;
constexpr float SCALE = 0.022097086912079612f;  // 1/sqrt(2048)
constexpr float NEGBIG = -3.402823466e38f;
}

__device__ float g_WQp[(size_t)S * S];
__device__ float g_Q[(size_t)B * S * D];
__device__ float g_V[(size_t)B * S * D];
__device__ float g_scores[(size_t)B * S * S];
__device__ float g_partM[B * 16 * S];
__device__ float g_partZ[B * 16 * S];
__device__ float g_colC[B * S];
__device__ float g_part[(size_t)KS * B * S * D];

typedef unsigned long long u64;

__device__ __forceinline__ u64 pack2(float lo, float hi) {
    u64 r;
    asm("mov.b64 %0, {%1, %2};" : "=l"(r) : "f"(lo), "f"(hi));
    return r;
}
__device__ __forceinline__ float2 unpack2(u64 v) {
    float2 r;
    asm("mov.b64 {%0, %1}, %2;" : "=f"(r.x), "=f"(r.y) : "l"(v));
    return r;
}
__device__ __forceinline__ void fma2(u64& d, u64 a, u64 b) {
    asm("fma.rn.f32x2 %0, %1, %2, %0;" : "+l"(d) : "l"(a), "l"(b));
}

// ---- k1: W_Q'[i,u] = sum_{t>=u} W_Q[i,t]/(t+1) --------------------------
__global__ __launch_bounds__(256) void k1_suffix(const float* __restrict__ WQ) {
    const int row = blockIdx.x, tid = threadIdx.x, base = tid * 8;
    const float* src = WQ + (size_t)row * S;
    float* dst = g_WQp + (size_t)row * S;
    float v[8], local = 0.f;
#pragma unroll
    for (int k = 0; k < 8; k++) { v[k] = src[base + k] / (float)(base + k + 1); local += v[k]; }
    float pre = local;
    const int lane = tid & 31, warp = tid >> 5;
#pragma unroll
    for (int off = 1; off < 32; off <<= 1) {
        float n = __shfl_up_sync(0xffffffff, pre, off);
        if (lane >= off) pre += n;
    }
    __shared__ float wsum[8], wpre[8], stot;
    if (lane == 31) wsum[warp] = pre;
    __syncthreads();
    if (tid == 0) {
        float acc = 0.f;
#pragma unroll
        for (int w = 0; w < 8; w++) { wpre[w] = acc; acc += wsum[w]; }
        stot = acc;
    }
    __syncthreads();
    float run = wpre[warp] + (pre - local);
#pragma unroll
    for (int k = 0; k < 8; k++) { dst[base + k] = stot - run; run += v[k]; }
}

// ---- k2: Q[b]=W_Q'@x[b] (z=0), V[b]=W_V@x[b] (z=1). M=2048,N=64,K=2048 ---
// m-paired FFMA2: A pairs natural from transposed As, B duplicated in smem.
__global__ __launch_bounds__(256) void k2_gemm_qv(const float* __restrict__ x,
                                                  const float* __restrict__ WV) {
    const int m0 = blockIdx.x * 128, b = blockIdx.y;
    const float* A = (blockIdx.z == 0) ? (const float*)g_WQp : WV;
    const float* xb = x + (size_t)b * S * D;
    float* C = ((blockIdx.z == 0) ? g_Q : g_V) + (size_t)b * S * D;
    __shared__ float As[16][132];
    __shared__ float Bsd[16][136];  // duplicated: Bsd[k][2n]=Bsd[k][2n+1]=B[k][n]
    const int tid = threadIdx.x, tx = tid & 7, ty = tid >> 3;
    const int arow = tid >> 1, akq = (tid & 1) * 8;
    const int bk = tid >> 4, bd = (tid & 15) * 4;
    u64 acc2[2][8];  // [m-pair][n]
#pragma unroll
    for (int i = 0; i < 2; i++)
#pragma unroll
        for (int j = 0; j < 8; j++) acc2[i][j] = 0ull;
    const float* ap = &A[(size_t)(m0 + arow) * S + akq];
    float4 ra0 = *(const float4*)ap, ra1 = *(const float4*)(ap + 4);
    float4 rb = *(const float4*)&xb[(size_t)bk * D + bd];
    for (int kt = 0; kt < S / 16; kt++) {
        As[akq + 0][arow] = ra0.x; As[akq + 1][arow] = ra0.y;
        As[akq + 2][arow] = ra0.z; As[akq + 3][arow] = ra0.w;
        As[akq + 4][arow] = ra1.x; As[akq + 5][arow] = ra1.y;
        As[akq + 6][arow] = ra1.z; As[akq + 7][arow] = ra1.w;
        *(float2*)&Bsd[bk][2 * bd + 0] = make_float2(rb.x, rb.x);
        *(float2*)&Bsd[bk][2 * bd + 2] = make_float2(rb.y, rb.y);
        *(float2*)&Bsd[bk][2 * bd + 4] = make_float2(rb.z, rb.z);
        *(float2*)&Bsd[bk][2 * bd + 6] = make_float2(rb.w, rb.w);
        __syncthreads();
        if (kt + 1 < S / 16) {
            const int k0 = (kt + 1) * 16;
            const float* p = &A[(size_t)(m0 + arow) * S + k0 + akq];
            ra0 = *(const float4*)p; ra1 = *(const float4*)(p + 4);
            rb = *(const float4*)&xb[(size_t)(k0 + bk) * D + bd];
        }
#pragma unroll
        for (int k = 0; k < 16; k++) {
            ulonglong2 aa = *(const ulonglong2*)&As[k][ty * 4];     // (m0,m1),(m2,m3)
            ulonglong2 b01 = *(const ulonglong2*)&Bsd[k][8 * tx];
            ulonglong2 b23 = *(const ulonglong2*)&Bsd[k][8 * tx + 4];
            ulonglong2 b45 = *(const ulonglong2*)&Bsd[k][64 + 8 * tx];
            ulonglong2 b67 = *(const ulonglong2*)&Bsd[k][64 + 8 * tx + 4];
            fma2(acc2[0][0], aa.x, b01.x); fma2(acc2[1][0], aa.y, b01.x);
            fma2(acc2[0][1], aa.x, b01.y); fma2(acc2[1][1], aa.y, b01.y);
            fma2(acc2[0][2], aa.x, b23.x); fma2(acc2[1][2], aa.y, b23.x);
            fma2(acc2[0][3], aa.x, b23.y); fma2(acc2[1][3], aa.y, b23.y);
            fma2(acc2[0][4], aa.x, b45.x); fma2(acc2[1][4], aa.y, b45.x);
            fma2(acc2[0][5], aa.x, b45.y); fma2(acc2[1][5], aa.y, b45.y);
            fma2(acc2[0][6], aa.x, b67.x); fma2(acc2[1][6], aa.y, b67.x);
            fma2(acc2[0][7], aa.x, b67.y); fma2(acc2[1][7], aa.y, b67.y);
        }
        __syncthreads();
    }
#pragma unroll
    for (int j = 0; j < 4; j++) {  // local m row
        const int mp = j >> 1, lane = j & 1;
        float v[8];
#pragma unroll
        for (int n = 0; n < 8; n++) {
            float2 p = unpack2(acc2[mp][n]);
            v[n] = lane ? p.y : p.x;
        }
        float* o = &C[(size_t)(m0 + ty * 4 + j) * D];
        *(float4*)&o[tx * 4] = make_float4(v[0], v[1], v[2], v[3]);
        *(float4*)&o[32 + tx * 4] = make_float4(v[4], v[5], v[6], v[7]);
    }
}

// ---- k3: masked scores + fused per-column (m,z) partials -----------------
__global__ __launch_bounds__(256) void k3_scores(const float* __restrict__ x) {
    const int i0 = blockIdx.x * 128, j0 = blockIdx.y * 128, b = blockIdx.z;
    const int tid = threadIdx.x;
    if (i0 + 127 < j0) {  // strictly upper block: write sentinel stats only
        if (tid < 128) {
            const size_t o = ((size_t)b * 16 + blockIdx.x) * S + j0 + tid;
            g_partM[o] = -1e38f;
            g_partZ[o] = 0.f;
        }
        return;
    }
    const float* Qb = g_Q + (size_t)b * S * D;
    const float* xb = x + (size_t)b * S * D;
    float* Sc = g_scores + (size_t)b * S * S;
    __shared__ float As[16][132];
    __shared__ float Bsd[16][264];  // duplicated B
    const int tx = tid & 15, ty = tid >> 4;
    const int lrow = tid >> 1, lk = (tid & 1) * 8;
    u64 acc2[4][8];  // [m-pair][n]
#pragma unroll
    for (int i = 0; i < 4; i++)
#pragma unroll
        for (int j = 0; j < 8; j++) acc2[i][j] = 0ull;
#pragma unroll
    for (int kt = 0; kt < D / 16; kt++) {
        const int k0 = kt * 16;
        const float* qp = &Qb[(size_t)(i0 + lrow) * D + k0 + lk];
        float4 q0 = *(const float4*)qp, q1 = *(const float4*)(qp + 4);
        const float* xp = &xb[(size_t)(j0 + lrow) * D + k0 + lk];
        float4 x0 = *(const float4*)xp, x1 = *(const float4*)(xp + 4);
        __syncthreads();
        As[lk + 0][lrow] = q0.x; As[lk + 1][lrow] = q0.y;
        As[lk + 2][lrow] = q0.z; As[lk + 3][lrow] = q0.w;
        As[lk + 4][lrow] = q1.x; As[lk + 5][lrow] = q1.y;
        As[lk + 6][lrow] = q1.z; As[lk + 7][lrow] = q1.w;
        *(float2*)&Bsd[lk + 0][2 * lrow] = make_float2(x0.x, x0.x);
        *(float2*)&Bsd[lk + 1][2 * lrow] = make_float2(x0.y, x0.y);
        *(float2*)&Bsd[lk + 2][2 * lrow] = make_float2(x0.z, x0.z);
        *(float2*)&Bsd[lk + 3][2 * lrow] = make_float2(x0.w, x0.w);
        *(float2*)&Bsd[lk + 4][2 * lrow] = make_float2(x1.x, x1.x);
        *(float2*)&Bsd[lk + 5][2 * lrow] = make_float2(x1.y, x1.y);
        *(float2*)&Bsd[lk + 6][2 * lrow] = make_float2(x1.z, x1.z);
        *(float2*)&Bsd[lk + 7][2 * lrow] = make_float2(x1.w, x1.w);
        __syncthreads();
#pragma unroll
        for (int k = 0; k < 16; k++) {
            ulonglong2 a03 = *(const ulonglong2*)&As[k][ty * 8];
            ulonglong2 a47 = *(const ulonglong2*)&As[k][ty * 8 + 4];
            ulonglong2 b01 = *(const ulonglong2*)&Bsd[k][8 * tx];
            ulonglong2 b23 = *(const ulonglong2*)&Bsd[k][8 * tx + 4];
            ulonglong2 b45 = *(const ulonglong2*)&Bsd[k][128 + 8 * tx];
            ulonglong2 b67 = *(const ulonglong2*)&Bsd[k][128 + 8 * tx + 4];
            const u64 am[4] = {a03.x, a03.y, a47.x, a47.y};
#pragma unroll
            for (int mp = 0; mp < 4; mp++) {
                fma2(acc2[mp][0], am[mp], b01.x);
                fma2(acc2[mp][1], am[mp], b01.y);
                fma2(acc2[mp][2], am[mp], b23.x);
                fma2(acc2[mp][3], am[mp], b23.y);
                fma2(acc2[mp][4], am[mp], b45.x);
                fma2(acc2[mp][5], am[mp], b45.y);
                fma2(acc2[mp][6], am[mp], b67.x);
                fma2(acc2[mp][7], am[mp], b67.y);
            }
        }
        __syncthreads();
    }
    // pass 1: mask, per-thread column maxima (scaled units)
    float mcol[8];
#pragma unroll
    for (int c = 0; c < 8; c++) mcol[c] = -1e38f;
#pragma unroll
    for (int mp = 0; mp < 4; mp++) {
        const int gi0 = i0 + ty * 8 + 2 * mp;
#pragma unroll
        for (int n = 0; n < 8; n++) {
            const int gj = j0 + ((n < 4) ? tx * 4 + n : 64 + tx * 4 + (n - 4));
            float2 v = unpack2(acc2[mp][n]);
            float o0 = (gi0 >= gj && v.x > 1.0f) ? v.x : NEGBIG;
            float o1 = (gi0 + 1 >= gj && v.y > 1.0f) ? v.y : NEGBIG;
            acc2[mp][n] = pack2(o0, o1);
            mcol[n] = fmaxf(mcol[n], fmaxf(o0, o1) * SCALE);
        }
    }
    // pass 2: write scores + accumulate z (mul-then-sub to match max rounding)
    float zcol[8];
#pragma unroll
    for (int c = 0; c < 8; c++) zcol[c] = 0.f;
#pragma unroll
    for (int mp = 0; mp < 4; mp++) {
        float2 p[8];
#pragma unroll
        for (int n = 0; n < 8; n++) p[n] = unpack2(acc2[mp][n]);
        const int gi0 = i0 + ty * 8 + 2 * mp;
        float* s0 = &Sc[(size_t)gi0 * S + j0];
        float* s1 = &Sc[(size_t)(gi0 + 1) * S + j0];
        *(float4*)&s0[tx * 4] = make_float4(p[0].x, p[1].x, p[2].x, p[3].x);
        *(float4*)&s0[64 + tx * 4] = make_float4(p[4].x, p[5].x, p[6].x, p[7].x);
        *(float4*)&s1[tx * 4] = make_float4(p[0].y, p[1].y, p[2].y, p[3].y);
        *(float4*)&s1[64 + tx * 4] = make_float4(p[4].y, p[5].y, p[6].y, p[7].y);
#pragma unroll
        for (int n = 0; n < 8; n++)
            zcol[n] += __expf(p[n].x * SCALE - mcol[n]) + __expf(p[n].y * SCALE - mcol[n]);
    }
    // reduce over the 16 ty-groups via smem (reuse As/Bsd as flat arrays)
    __syncthreads();
    float* red_m = &As[0][0];
    float* red_z = &Bsd[0][0];
#pragma unroll
    for (int n = 0; n < 8; n++) {
        const int col = (n < 4) ? (tx * 4 + n) : (64 + tx * 4 + n - 4);
        red_m[ty * 128 + col] = mcol[n];
        red_z[ty * 128 + col] = zcol[n];
    }
    __syncthreads();
    if (tid < 128) {
        float m = -1e38f;
#pragma unroll
        for (int t = 0; t < 16; t++) m = fmaxf(m, red_m[t * 128 + tid]);
        float z = 0.f;
#pragma unroll
        for (int t = 0; t < 16; t++) z += red_z[t * 128 + tid] * __expf(red_m[t * 128 + tid] - m);
        const size_t o = ((size_t)b * 16 + blockIdx.x) * S + j0 + tid;
        g_partM[o] = m;
        g_partZ[o] = z;
    }
}

// ---- k4b: reduce 16 partials -> colC[j] = m_j + log(z_j), full MLP -------
__global__ __launch_bounds__(256) void k4b_reduce() {
    const int j = blockIdx.x * 256 + threadIdx.x, b = blockIdx.y;
    float pm[16], pz[16];
#pragma unroll
    for (int i = 0; i < 16; i++) {
        pm[i] = g_partM[((size_t)b * 16 + i) * S + j];
        pz[i] = g_partZ[((size_t)b * 16 + i) * S + j];
    }
    float m = -1e38f;
#pragma unroll
    for (int i = 0; i < 16; i++) m = fmaxf(m, pm[i]);
    float z = 0.f;
#pragma unroll
    for (int i = 0; i < 16; i++) z += pz[i] * __expf(pm[i] - m);
    g_colC[b * S + j] = m + logf(z);
}

// ---- k5: partial out = exp(s*scale - colC_j) @ V, split-K over j-tiles ---
__global__ __launch_bounds__(256) void k5_pv() {
    const int mb = blockIdx.x, sp = blockIdx.y, b = blockIdx.z;
    const int i0 = mb * 128;
    const float* Sc = g_scores + (size_t)b * S * S;
    const float* Vb = g_V + (size_t)b * S * D;
    const float* cC = g_colC + b * S;
    float* P = g_part + (size_t)(sp * B + b) * S * D;
    __shared__ float As[16][132];
    __shared__ float Bsd[16][136];
    const int tid = threadIdx.x, tx = tid & 7, ty = tid >> 3;
    const int arow = tid >> 1, akq = (tid & 1) * 8;
    const int bk = tid >> 4, bd = (tid & 15) * 4;
    u64 acc2[2][8];
#pragma unroll
    for (int i = 0; i < 2; i++)
#pragma unroll
        for (int j = 0; j < 8; j++) acc2[i][j] = 0ull;
    for (int t = sp; t <= mb; t += KS) {
#pragma unroll 1
        for (int kk = 0; kk < 8; kk++) {
            const int k0 = t * 128 + kk * 16;
            const float* ap = &Sc[(size_t)(i0 + arow) * S + k0 + akq];
            float4 a0 = *(const float4*)ap, a1 = *(const float4*)(ap + 4);
            float4 c0 = *(const float4*)&cC[k0 + akq];
            float4 c1 = *(const float4*)&cC[k0 + akq + 4];
            float4 vb = *(const float4*)&Vb[(size_t)(k0 + bk) * D + bd];
            __syncthreads();
            As[akq + 0][arow] = __expf(fmaf(a0.x, SCALE, -c0.x));
            As[akq + 1][arow] = __expf(fmaf(a0.y, SCALE, -c0.y));
            As[akq + 2][arow] = __expf(fmaf(a0.z, SCALE, -c0.z));
            As[akq + 3][arow] = __expf(fmaf(a0.w, SCALE, -c0.w));
            As[akq + 4][arow] = __expf(fmaf(a1.x, SCALE, -c1.x));
            As[akq + 5][arow] = __expf(fmaf(a1.y, SCALE, -c1.y));
            As[akq + 6][arow] = __expf(fmaf(a1.z, SCALE, -c1.z));
            As[akq + 7][arow] = __expf(fmaf(a1.w, SCALE, -c1.w));
            *(float2*)&Bsd[bk][2 * bd + 0] = make_float2(vb.x, vb.x);
            *(float2*)&Bsd[bk][2 * bd + 2] = make_float2(vb.y, vb.y);
            *(float2*)&Bsd[bk][2 * bd + 4] = make_float2(vb.z, vb.z);
            *(float2*)&Bsd[bk][2 * bd + 6] = make_float2(vb.w, vb.w);
            __syncthreads();
#pragma unroll
            for (int k = 0; k < 16; k++) {
                ulonglong2 aa = *(const ulonglong2*)&As[k][ty * 4];
                ulonglong2 b01 = *(const ulonglong2*)&Bsd[k][8 * tx];
                ulonglong2 b23 = *(const ulonglong2*)&Bsd[k][8 * tx + 4];
                ulonglong2 b45 = *(const ulonglong2*)&Bsd[k][64 + 8 * tx];
                ulonglong2 b67 = *(const ulonglong2*)&Bsd[k][64 + 8 * tx + 4];
                fma2(acc2[0][0], aa.x, b01.x); fma2(acc2[1][0], aa.y, b01.x);
                fma2(acc2[0][1], aa.x, b01.y); fma2(acc2[1][1], aa.y, b01.y);
                fma2(acc2[0][2], aa.x, b23.x); fma2(acc2[1][2], aa.y, b23.x);
                fma2(acc2[0][3], aa.x, b23.y); fma2(acc2[1][3], aa.y, b23.y);
                fma2(acc2[0][4], aa.x, b45.x); fma2(acc2[1][4], aa.y, b45.x);
                fma2(acc2[0][5], aa.x, b45.y); fma2(acc2[1][5], aa.y, b45.y);
                fma2(acc2[0][6], aa.x, b67.x); fma2(acc2[1][6], aa.y, b67.x);
                fma2(acc2[0][7], aa.x, b67.y); fma2(acc2[1][7], aa.y, b67.y);
            }
        }
    }
#pragma unroll
    for (int j = 0; j < 4; j++) {
        const int mp = j >> 1, lane = j & 1;
        float v[8];
#pragma unroll
        for (int n = 0; n < 8; n++) {
            float2 p = unpack2(acc2[mp][n]);
            v[n] = lane ? p.y : p.x;
        }
        float* o = &P[(size_t)(i0 + ty * 4 + j) * D];
        *(float4*)&o[tx * 4] = make_float4(v[0], v[1], v[2], v[3]);
        *(float4*)&o[32 + tx * 4] = make_float4(v[4], v[5], v[6], v[7]);
    }
}

// ---- k6: reduce KS split-K partials into d_out ---------------------------
__global__ __launch_bounds__(256) void k6_reduce(float* __restrict__ out) {
    const int idx = blockIdx.x * 256 + threadIdx.x;  // float4 index
    const float4* p = (const float4*)g_part;
    const size_t n4 = (size_t)B * S * D / 4;
    float4 a = p[idx];
#pragma unroll
    for (int sp = 1; sp < KS; sp++) {
        float4 q = p[sp * n4 + idx];
        a.x += q.x; a.y += q.y; a.z += q.z; a.w += q.w;
    }
    ((float4*)out)[idx] = a;
}

extern "C" void kernel_launch(void* const* d_in, const int* in_sizes, int n_in,
                              void* d_out, int out_size) {
    int xi = 0;
    for (int i = 0; i < n_in; i++)
        if (in_sizes[i] == B * S * D) { xi = i; break; }
    int o1 = -1, o2 = -1;
    for (int i = 0; i < n_in; i++)
        if (i != xi) { if (o1 < 0) o1 = i; else o2 = i; }
    const float* x = (const float*)d_in[xi];
    const float* WQ = (const float*)d_in[o1];
    const float* WV = (const float*)d_in[o2];

    k1_suffix<<<S, 256>>>(WQ);
    k2_gemm_qv<<<dim3(16, B, 2), 256>>>(x, WV);
    k3_scores<<<dim3(16, 16, B), 256>>>(x);
    k4b_reduce<<<dim3(S / 256, B), 256>>>();
    k5_pv<<<dim3(16, KS, B), 256>>>();
    k6_reduce<<<(B * S * D / 4) / 256, 256>>>((float*)d_out);
}

// round 8
// speedup vs baseline: 2.0011x; 2.0011x over previous
#include <cuda_runtime.h>

namespace {
constexpr int B = 4, S = 2048, D = 64, KS = 8;
constexpr float SCALE = 0.022097086912079612f;  // 1/sqrt(2048)
constexpr float NEGBIG = -3.402823466e38f;
}

__device__ float g_WQp[(size_t)S * S];
__device__ float g_Q[(size_t)B * S * D];
__device__ float g_V[(size_t)B * S * D];
__device__ float g_scores[(size_t)B * S * S];
__device__ float g_partM[B * 16 * S];
__device__ float g_partZ[B * 16 * S];
__device__ float g_colC[B * S];
__device__ float g_part[(size_t)KS * B * S * D];

// ---- k1: W_Q'[i,u] = sum_{t>=u} W_Q[i,t]/(t+1) --------------------------
__global__ __launch_bounds__(256) void k1_suffix(const float* __restrict__ WQ) {
    const int row = blockIdx.x, tid = threadIdx.x, base = tid * 8;
    const float* src = WQ + (size_t)row * S;
    float* dst = g_WQp + (size_t)row * S;
    float v[8], local = 0.f;
#pragma unroll
    for (int k = 0; k < 8; k++) { v[k] = src[base + k] / (float)(base + k + 1); local += v[k]; }
    float pre = local;
    const int lane = tid & 31, warp = tid >> 5;
#pragma unroll
    for (int off = 1; off < 32; off <<= 1) {
        float n = __shfl_up_sync(0xffffffff, pre, off);
        if (lane >= off) pre += n;
    }
    __shared__ float wsum[8], wpre[8], stot;
    if (lane == 31) wsum[warp] = pre;
    __syncthreads();
    if (tid == 0) {
        float acc = 0.f;
#pragma unroll
        for (int w = 0; w < 8; w++) { wpre[w] = acc; acc += wsum[w]; }
        stot = acc;
    }
    __syncthreads();
    float run = wpre[warp] + (pre - local);
#pragma unroll
    for (int k = 0; k < 8; k++) { dst[base + k] = stot - run; run += v[k]; }
}

// ---- k2: Q[b]=W_Q'@x[b] (z=0), V[b]=W_V@x[b] (z=1). M=2048,N=64,K=2048 ---
__global__ __launch_bounds__(256) void k2_gemm_qv(const float* __restrict__ x,
                                                  const float* __restrict__ WV) {
    const int m0 = blockIdx.x * 128, b = blockIdx.y;
    const float* A = (blockIdx.z == 0) ? (const float*)g_WQp : WV;
    const float* xb = x + (size_t)b * S * D;
    float* C = ((blockIdx.z == 0) ? g_Q : g_V) + (size_t)b * S * D;
    __shared__ float As[16][132];
    __shared__ float Bs[16][64];
    const int tid = threadIdx.x, tx = tid & 7, ty = tid >> 3;
    const int arow = tid >> 1, akq = (tid & 1) * 8;
    const int bk = tid >> 4, bd = (tid & 15) * 4;
    float acc[4][8];
#pragma unroll
    for (int i = 0; i < 4; i++)
#pragma unroll
        for (int j = 0; j < 8; j++) acc[i][j] = 0.f;
    const float* ap = &A[(size_t)(m0 + arow) * S + akq];
    float4 ra0 = *(const float4*)ap, ra1 = *(const float4*)(ap + 4);
    float4 rb = *(const float4*)&xb[(size_t)bk * D + bd];
    for (int kt = 0; kt < S / 16; kt++) {
        As[akq + 0][arow] = ra0.x; As[akq + 1][arow] = ra0.y;
        As[akq + 2][arow] = ra0.z; As[akq + 3][arow] = ra0.w;
        As[akq + 4][arow] = ra1.x; As[akq + 5][arow] = ra1.y;
        As[akq + 6][arow] = ra1.z; As[akq + 7][arow] = ra1.w;
        *(float4*)&Bs[bk][bd] = rb;
        __syncthreads();
        if (kt + 1 < S / 16) {
            const int k0 = (kt + 1) * 16;
            const float* p = &A[(size_t)(m0 + arow) * S + k0 + akq];
            ra0 = *(const float4*)p; ra1 = *(const float4*)(p + 4);
            rb = *(const float4*)&xb[(size_t)(k0 + bk) * D + bd];
        }
#pragma unroll
        for (int k = 0; k < 16; k++) {
            float4 a4 = *(const float4*)&As[k][ty * 4];
            float4 b0 = *(const float4*)&Bs[k][tx * 4];
            float4 b1 = *(const float4*)&Bs[k][32 + tx * 4];
            float av[4] = {a4.x, a4.y, a4.z, a4.w};
            float bv[8] = {b0.x, b0.y, b0.z, b0.w, b1.x, b1.y, b1.z, b1.w};
#pragma unroll
            for (int i = 0; i < 4; i++)
#pragma unroll
                for (int j = 0; j < 8; j++) acc[i][j] = fmaf(av[i], bv[j], acc[i][j]);
        }
        __syncthreads();
    }
#pragma unroll
    for (int i = 0; i < 4; i++) {
        float* o = &C[(size_t)(m0 + ty * 4 + i) * D];
        *(float4*)&o[tx * 4] = make_float4(acc[i][0], acc[i][1], acc[i][2], acc[i][3]);
        *(float4*)&o[32 + tx * 4] = make_float4(acc[i][4], acc[i][5], acc[i][6], acc[i][7]);
    }
}

// ---- k3: masked scores + fused per-column (m,z) partials -----------------
// keep iff i>=j && s>1, else -FLT_MAX. Writes g_partM/g_partZ[(b*16+ibk)*S+j].
__global__ __launch_bounds__(256) void k3_scores(const float* __restrict__ x) {
    const int i0 = blockIdx.x * 128, j0 = blockIdx.y * 128, b = blockIdx.z;
    const int tid = threadIdx.x;
    if (i0 + 127 < j0) {  // strictly upper block: sentinel stats, no scores
        if (tid < 128) {
            const size_t o = ((size_t)b * 16 + blockIdx.x) * S + j0 + tid;
            g_partM[o] = -1e38f;
            g_partZ[o] = 0.f;
        }
        return;
    }
    const float* Qb = g_Q + (size_t)b * S * D;
    const float* xb = x + (size_t)b * S * D;
    float* Sc = g_scores + (size_t)b * S * S;
    __shared__ float As[16][132], Bs[16][132];
    const int tx = tid & 15, ty = tid >> 4;
    const int lrow = tid >> 1, lk = (tid & 1) * 8;
    float acc[8][8];
#pragma unroll
    for (int i = 0; i < 8; i++)
#pragma unroll
        for (int j = 0; j < 8; j++) acc[i][j] = 0.f;
#pragma unroll
    for (int kt = 0; kt < D / 16; kt++) {
        const int k0 = kt * 16;
        const float* qp = &Qb[(size_t)(i0 + lrow) * D + k0 + lk];
        float4 q0 = *(const float4*)qp, q1 = *(const float4*)(qp + 4);
        const float* xp = &xb[(size_t)(j0 + lrow) * D + k0 + lk];
        float4 x0 = *(const float4*)xp, x1 = *(const float4*)(xp + 4);
        __syncthreads();
        As[lk + 0][lrow] = q0.x; As[lk + 1][lrow] = q0.y;
        As[lk + 2][lrow] = q0.z; As[lk + 3][lrow] = q0.w;
        As[lk + 4][lrow] = q1.x; As[lk + 5][lrow] = q1.y;
        As[lk + 6][lrow] = q1.z; As[lk + 7][lrow] = q1.w;
        Bs[lk + 0][lrow] = x0.x; Bs[lk + 1][lrow] = x0.y;
        Bs[lk + 2][lrow] = x0.z; Bs[lk + 3][lrow] = x0.w;
        Bs[lk + 4][lrow] = x1.x; Bs[lk + 5][lrow] = x1.y;
        Bs[lk + 6][lrow] = x1.z; Bs[lk + 7][lrow] = x1.w;
        __syncthreads();
#pragma unroll
        for (int k = 0; k < 16; k++) {
            float4 a0 = *(const float4*)&As[k][ty * 8];
            float4 a1 = *(const float4*)&As[k][ty * 8 + 4];
            float4 b0 = *(const float4*)&Bs[k][tx * 4];
            float4 b1 = *(const float4*)&Bs[k][64 + tx * 4];
            float av[8] = {a0.x, a0.y, a0.z, a0.w, a1.x, a1.y, a1.z, a1.w};
            float bv[8] = {b0.x, b0.y, b0.z, b0.w, b1.x, b1.y, b1.z, b1.w};
#pragma unroll
            for (int i = 0; i < 8; i++)
#pragma unroll
                for (int j = 0; j < 8; j++) acc[i][j] = fmaf(av[i], bv[j], acc[i][j]);
        }
        __syncthreads();
    }
    // pass 1: mask in-place; track per-thread column maxima in scaled units.
    // sc[] holds the scaled value used for BOTH max and exp (no fma contraction
    // mismatch -> exp argument at the max is exactly 0).
    float mcol[8];
#pragma unroll
    for (int c = 0; c < 8; c++) mcol[c] = -1e38f;
    float sc[8][8];
#pragma unroll
    for (int r = 0; r < 8; r++) {
        const int gi = i0 + ty * 8 + r;
#pragma unroll
        for (int c = 0; c < 8; c++) {
            const int gj = j0 + ((c < 4) ? tx * 4 + c : 64 + tx * 4 + (c - 4));
            const float v = acc[r][c];
            const float o = (gi >= gj && v > 1.0f) ? v : NEGBIG;
            acc[r][c] = o;
            const float s = o * SCALE;
            sc[r][c] = s;
            mcol[c] = fmaxf(mcol[c], s);
        }
    }
    // pass 2: write scores + accumulate z
    float zcol[8];
#pragma unroll
    for (int c = 0; c < 8; c++) zcol[c] = 0.f;
#pragma unroll
    for (int r = 0; r < 8; r++) {
        const int gi = i0 + ty * 8 + r;
        float* sp = &Sc[(size_t)gi * S + j0];
        *(float4*)&sp[tx * 4] = make_float4(acc[r][0], acc[r][1], acc[r][2], acc[r][3]);
        *(float4*)&sp[64 + tx * 4] = make_float4(acc[r][4], acc[r][5], acc[r][6], acc[r][7]);
#pragma unroll
        for (int c = 0; c < 8; c++) zcol[c] += __expf(sc[r][c] - mcol[c]);
    }
    // reduce over the 16 ty-groups via smem (reuse As/Bs as flat arrays)
    __syncthreads();
    float* red_m = &As[0][0];
    float* red_z = &Bs[0][0];
#pragma unroll
    for (int c = 0; c < 8; c++) {
        const int col = (c < 4) ? (tx * 4 + c) : (64 + tx * 4 + c - 4);
        red_m[ty * 128 + col] = mcol[c];
        red_z[ty * 128 + col] = zcol[c];
    }
    __syncthreads();
    if (tid < 128) {
        float m = -1e38f;
#pragma unroll
        for (int t = 0; t < 16; t++) m = fmaxf(m, red_m[t * 128 + tid]);
        float z = 0.f;
#pragma unroll
        for (int t = 0; t < 16; t++) z += red_z[t * 128 + tid] * __expf(red_m[t * 128 + tid] - m);
        const size_t o = ((size_t)b * 16 + blockIdx.x) * S + j0 + tid;
        g_partM[o] = m;
        g_partZ[o] = z;
    }
}

// ---- k4b: reduce 16 partials -> colC[j] = m_j + log(z_j), full MLP -------
__global__ __launch_bounds__(256) void k4b_reduce() {
    const int j = blockIdx.x * 256 + threadIdx.x, b = blockIdx.y;
    float pm[16], pz[16];
#pragma unroll
    for (int i = 0; i < 16; i++) {
        pm[i] = g_partM[((size_t)b * 16 + i) * S + j];
        pz[i] = g_partZ[((size_t)b * 16 + i) * S + j];
    }
    float m = -1e38f;
#pragma unroll
    for (int i = 0; i < 16; i++) m = fmaxf(m, pm[i]);
    float z = 0.f;
#pragma unroll
    for (int i = 0; i < 16; i++) z += pz[i] * __expf(pm[i] - m);
    g_colC[b * S + j] = m + logf(z);
}

// ---- k5: partial out = exp(s*scale - colC_j) @ V, split-K over j-tiles ---
__global__ __launch_bounds__(256) void k5_pv() {
    const int mb = blockIdx.x, sp = blockIdx.y, b = blockIdx.z;
    const int i0 = mb * 128;
    const float* Sc = g_scores + (size_t)b * S * S;
    const float* Vb = g_V + (size_t)b * S * D;
    const float* cC = g_colC + b * S;
    float* P = g_part + (size_t)(sp * B + b) * S * D;
    __shared__ float As[16][132];
    __shared__ float Bs[16][64];
    const int tid = threadIdx.x, tx = tid & 7, ty = tid >> 3;
    const int arow = tid >> 1, akq = (tid & 1) * 8;
    const int bk = tid >> 4, bd = (tid & 15) * 4;
    float acc[4][8];
#pragma unroll
    for (int i = 0; i < 4; i++)
#pragma unroll
        for (int j = 0; j < 8; j++) acc[i][j] = 0.f;
    for (int t = sp; t <= mb; t += KS) {
#pragma unroll 1
        for (int kk = 0; kk < 8; kk++) {
            const int k0 = t * 128 + kk * 16;
            const float* ap = &Sc[(size_t)(i0 + arow) * S + k0 + akq];
            float4 a0 = *(const float4*)ap, a1 = *(const float4*)(ap + 4);
            float4 c0 = *(const float4*)&cC[k0 + akq];
            float4 c1 = *(const float4*)&cC[k0 + akq + 4];
            float4 vb = *(const float4*)&Vb[(size_t)(k0 + bk) * D + bd];
            __syncthreads();
            As[akq + 0][arow] = __expf(fmaf(a0.x, SCALE, -c0.x));
            As[akq + 1][arow] = __expf(fmaf(a0.y, SCALE, -c0.y));
            As[akq + 2][arow] = __expf(fmaf(a0.z, SCALE, -c0.z));
            As[akq + 3][arow] = __expf(fmaf(a0.w, SCALE, -c0.w));
            As[akq + 4][arow] = __expf(fmaf(a1.x, SCALE, -c1.x));
            As[akq + 5][arow] = __expf(fmaf(a1.y, SCALE, -c1.y));
            As[akq + 6][arow] = __expf(fmaf(a1.z, SCALE, -c1.z));
            As[akq + 7][arow] = __expf(fmaf(a1.w, SCALE, -c1.w));
            *(float4*)&Bs[bk][bd] = vb;
            __syncthreads();
#pragma unroll
            for (int k = 0; k < 16; k++) {
                float4 a4 = *(const float4*)&As[k][ty * 4];
                float4 b0 = *(const float4*)&Bs[k][tx * 4];
                float4 b1 = *(const float4*)&Bs[k][32 + tx * 4];
                float av[4] = {a4.x, a4.y, a4.z, a4.w};
                float bv[8] = {b0.x, b0.y, b0.z, b0.w, b1.x, b1.y, b1.z, b1.w};
#pragma unroll
                for (int i = 0; i < 4; i++)
#pragma unroll
                    for (int j = 0; j < 8; j++) acc[i][j] = fmaf(av[i], bv[j], acc[i][j]);
            }
        }
    }
#pragma unroll
    for (int i = 0; i < 4; i++) {
        float* o = &P[(size_t)(i0 + ty * 4 + i) * D];
        *(float4*)&o[tx * 4] = make_float4(acc[i][0], acc[i][1], acc[i][2], acc[i][3]);
        *(float4*)&o[32 + tx * 4] = make_float4(acc[i][4], acc[i][5], acc[i][6], acc[i][7]);
    }
}

// ---- k6: reduce KS split-K partials into d_out ---------------------------
__global__ __launch_bounds__(256) void k6_reduce(float* __restrict__ out) {
    const int idx = blockIdx.x * 256 + threadIdx.x;  // float4 index
    const float4* p = (const float4*)g_part;
    const size_t n4 = (size_t)B * S * D / 4;
    float4 a = p[idx];
#pragma unroll
    for (int sp = 1; sp < KS; sp++) {
        float4 q = p[sp * n4 + idx];
        a.x += q.x; a.y += q.y; a.z += q.z; a.w += q.w;
    }
    ((float4*)out)[idx] = a;
}

extern "C" void kernel_launch(void* const* d_in, const int* in_sizes, int n_in,
                              void* d_out, int out_size) {
    int xi = 0;
    for (int i = 0; i < n_in; i++)
        if (in_sizes[i] == B * S * D) { xi = i; break; }
    int o1 = -1, o2 = -1;
    for (int i = 0; i < n_in; i++)
        if (i != xi) { if (o1 < 0) o1 = i; else o2 = i; }
    const float* x = (const float*)d_in[xi];
    const float* WQ = (const float*)d_in[o1];
    const float* WV = (const float*)d_in[o2];

    k1_suffix<<<S, 256>>>(WQ);
    k2_gemm_qv<<<dim3(16, B, 2), 256>>>(x, WV);
    k3_scores<<<dim3(16, 16, B), 256>>>(x);
    k4b_reduce<<<dim3(S / 256, B), 256>>>();
    k5_pv<<<dim3(16, KS, B), 256>>>();
    k6_reduce<<<(B * S * D / 4) / 256, 256>>>((float*)d_out);
}